// round 12
// baseline (speedup 1.0000x reference)
#include <cuda_runtime.h>

#define HD   128
#define NMAX 50000
#define EMAX 600000
#define GMAX 128
#define CLS  10
#define SCAN_B 256

// ---------------- scratch ----------------
__device__ __align__(16) float g_deg [NMAX];          // dinv
__device__ __align__(16) int   g_cnti[NMAX];          // in-degree histogram
__device__ __align__(16) int   g_roff[NMAX + 1];      // CSR offsets
__device__ __align__(16) int   g_cur [NMAX];          // fill cursors
__device__ __align__(16) int   g_bsum[(NMAX + SCAN_B - 1) / SCAN_B];
__device__ __align__(16) int   g_csrc[EMAX];          // CSR src
__device__ __align__(16) float g_cnorm[EMAX];         // CSR norm
__device__ __align__(16) int   g_gstart[GMAX + 1];    // graph node ranges (batch sorted)
__device__ __align__(16) float g_lin[(size_t)NMAX * HD];
__device__ __align__(16) float g_h1 [(size_t)NMAX * HD];
__device__ __align__(16) float g_h2 [(size_t)NMAX * HD];
__device__ int g_is64;

__device__ __forceinline__ int ldidx(const void* p, size_t i) {
    return g_is64 ? (int)((const long long*)p)[i] : ((const int*)p)[i];
}

// ---------------- f32x2 helpers ----------------
#define FMA2(d, a, b) \
    asm("fma.rn.f32x2 %0, %1, %2, %3;" : "=l"(d) : "l"(a), "l"(b), "l"(d))
#define DUP2(d, f) \
    asm("mov.b64 %0, {%1, %1};" : "=l"(d) : "f"(f))
__device__ __forceinline__ void upk(unsigned long long p, float& lo, float& hi) {
    asm("mov.b64 {%0, %1}, %2;" : "=f"(lo), "=f"(hi) : "l"(p));
}

// ---------------- setup: zero histogram + dtype detect ----------
__global__ void k_setup(const unsigned* __restrict__ w, int E, int n) {
    int i = blockIdx.x * blockDim.x + threadIdx.x;
    if (i < n) g_cnti[i] = 0;
    if (blockIdx.x == 0) {
        int cnt = E < 256 ? E : 256;
        int t = threadIdx.x;
        int ok = (t < cnt) ? (w[2 * t + 1] == 0u) : 1;
        ok = __syncthreads_and(ok);
        if (t == 0) g_is64 = ok;
    }
}
// graph ranges from sorted batch: pure boundary writes, no atomics
__global__ void k_bounds(const void* __restrict__ batch, int n, int G) {
    int i = blockIdx.x * blockDim.x + threadIdx.x;
    if (i >= n) return;
    int g = ldidx(batch, i);
    if (i == 0) {
        for (int q = 0; q <= g; q++) g_gstart[q] = 0;
    } else {
        int gp = ldidx(batch, i - 1);
        for (int q = gp + 1; q <= g; q++) g_gstart[q] = i;
    }
    if (i == n - 1) {
        for (int q = g + 1; q <= G; q++) g_gstart[q] = n;
    }
}
__global__ void k_hist(const void* __restrict__ ei, int E) {
    int e = blockIdx.x * blockDim.x + threadIdx.x;
    if (e < E) atomicAdd(&g_cnti[ldidx(ei, (size_t)E + e)], 1);
}
// block-wise exclusive scan of g_cnti -> g_roff (+ fused dinv)
__global__ void k_scan1(int n) {
    __shared__ int s[SCAN_B];
    int i = blockIdx.x * SCAN_B + threadIdx.x;
    int v = (i < n) ? g_cnti[i] : 0;
    if (i < n) g_deg[i] = rsqrtf(1.0f + (float)v);
    s[threadIdx.x] = v;
    __syncthreads();
    int acc = v;
#pragma unroll
    for (int off = 1; off < SCAN_B; off <<= 1) {
        int add = (threadIdx.x >= off) ? s[threadIdx.x - off] : 0;
        __syncthreads();
        acc += add;
        s[threadIdx.x] = acc;
        __syncthreads();
    }
    if (i < n) g_roff[i] = acc - v;
    if (threadIdx.x == SCAN_B - 1) g_bsum[blockIdx.x] = acc;
}
__global__ void k_scan2(int nb) {
    __shared__ int s[SCAN_B];
    int t = threadIdx.x;
    int v = (t < nb) ? g_bsum[t] : 0;
    s[t] = v;
    __syncthreads();
    int acc = v;
#pragma unroll
    for (int off = 1; off < SCAN_B; off <<= 1) {
        int add = (t >= off) ? s[t - off] : 0;
        __syncthreads();
        acc += add;
        s[t] = acc;
        __syncthreads();
    }
    if (t < nb) g_bsum[t] = acc - v;
}
__global__ void k_scan3(int n, int E) {
    int i = blockIdx.x * blockDim.x + threadIdx.x;
    if (i < n) {
        int r = g_roff[i] + g_bsum[i >> 8];
        g_roff[i] = r;
        g_cur[i] = r;
    }
    if (i == 0) g_roff[n] = E;
}
__global__ void k_fill(const void* __restrict__ ei, int E) {
    int e = blockIdx.x * blockDim.x + threadIdx.x;
    if (e >= E) return;
    int s = ldidx(ei, e);
    int d = ldidx(ei, (size_t)E + e);
    int pos = atomicAdd(&g_cur[d], 1);
    g_csrc[pos] = s;
    g_cnorm[pos] = g_deg[s] * g_deg[d];
}

// ---------------- GEMM: g_lin = A @ W  (persistent tile loop) ----------------
// Block 128x128 tile, 256 thr = 8 warps (4x2), warp tile 32x64, lane 8x8.
// Grid = 2*#SM CTAs; each CTA strides over row tiles -> no wave-quantization
// tail. Double-buffer parity: kc=15's barrier orders the next tile's first
// STS(buf0) against all compute(buf0) from kc=14, so NO extra cross-tile sync.
__global__ __launch_bounds__(256) void k_gemm(
    const float* __restrict__ Ax, int aSel,
    const float* __restrict__ W, int M, int nTiles)
{
    const float* A = (aSel == 0) ? Ax : (aSel == 1 ? g_h1 : g_h2);

    __shared__ __align__(16) float sA[2][8][132];
    __shared__ __align__(16) float sB[2][8][128];

    const int tid  = threadIdx.x;
    const int wid  = tid >> 5, lane = tid & 31;
    const int m0   = (wid & 3) * 32 + (lane >> 3) * 8;
    const int n0   = (wid >> 2) * 64 + (lane & 7) * 8;

    const int am = tid >> 1;
    const int ak = (tid & 1) * 4;
    const int bn = (tid & 31) * 4;
    const int bk = tid >> 5;

    int buf = 0;
    for (int tile = blockIdx.x; tile < nTiles; tile += gridDim.x) {
        const int rowBase = tile << 7;
        const int arow = rowBase + am;

        unsigned long long acc[4][8];
#pragma unroll
        for (int rp = 0; rp < 4; rp++)
#pragma unroll
            for (int j = 0; j < 8; j++) acc[rp][j] = 0ull;

        auto ldA = [&](int kc) -> float4 {
            if (arow < M)
                return *(const float4*)(A + (size_t)arow * HD + kc * 8 + ak);
            return make_float4(0.f, 0.f, 0.f, 0.f);
        };
        auto ldB = [&](int kc) -> float4 {
            return *(const float4*)(W + (size_t)(kc * 8 + bk) * HD + bn);
        };

        float4 ra = ldA(0), rb = ldB(0);
#pragma unroll 1
        for (int kc = 0; kc < 16; kc++) {
            sA[buf][ak + 0][am] = ra.x;
            sA[buf][ak + 1][am] = ra.y;
            sA[buf][ak + 2][am] = ra.z;
            sA[buf][ak + 3][am] = ra.w;
            *(float4*)&sB[buf][bk][bn] = rb;
            __syncthreads();
            if (kc < 15) { ra = ldA(kc + 1); rb = ldB(kc + 1); }
#pragma unroll
            for (int k = 0; k < 8; k++) {
                float4 a0 = *(const float4*)&sA[buf][k][m0];
                float4 a1 = *(const float4*)&sA[buf][k][m0 + 4];
                float4 b0 = *(const float4*)&sB[buf][k][n0];
                float4 b1 = *(const float4*)&sB[buf][k][n0 + 4];
                unsigned long long A2[4], B2[8];
                A2[0] = ((const ulonglong2*)&a0)->x;
                A2[1] = ((const ulonglong2*)&a0)->y;
                A2[2] = ((const ulonglong2*)&a1)->x;
                A2[3] = ((const ulonglong2*)&a1)->y;
                DUP2(B2[0], b0.x); DUP2(B2[1], b0.y);
                DUP2(B2[2], b0.z); DUP2(B2[3], b0.w);
                DUP2(B2[4], b1.x); DUP2(B2[5], b1.y);
                DUP2(B2[6], b1.z); DUP2(B2[7], b1.w);
#pragma unroll
                for (int rp = 0; rp < 4; rp++)
#pragma unroll
                    for (int j = 0; j < 8; j++)
                        FMA2(acc[rp][j], A2[rp], B2[j]);
            }
            buf ^= 1;
        }

#pragma unroll
        for (int rp = 0; rp < 4; rp++) {
            float lo[8], hi[8];
#pragma unroll
            for (int j = 0; j < 8; j++) upk(acc[rp][j], lo[j], hi[j]);
            int r0 = rowBase + m0 + 2 * rp;
            if (r0 < M) {
                *(float4*)(g_lin + (size_t)r0 * HD + n0)     = make_float4(lo[0], lo[1], lo[2], lo[3]);
                *(float4*)(g_lin + (size_t)r0 * HD + n0 + 4) = make_float4(lo[4], lo[5], lo[6], lo[7]);
            }
            if (r0 + 1 < M) {
                *(float4*)(g_lin + (size_t)(r0 + 1) * HD + n0)     = make_float4(hi[0], hi[1], hi[2], hi[3]);
                *(float4*)(g_lin + (size_t)(r0 + 1) * HD + n0 + 4) = make_float4(hi[4], hi[5], hi[6], hi[7]);
            }
        }
    }
}

// ---------------- CSR gather: h[i] = relu(b + dinv_i^2*lin[i] + sum norm*lin[src]) ----
__global__ __launch_bounds__(256) void k_gather(
    const float* __restrict__ bias, int outSel, int n)
{
    int i = blockIdx.x * 8 + (threadIdx.x >> 5);
    if (i >= n) return;
    int c = (threadIdx.x & 31) * 4;

    float di = g_deg[i];
    float sn = di * di;
    float4 acc = __ldg((const float4*)(bias + c));
    float4 sv = *(const float4*)(g_lin + (size_t)i * HD + c);
    acc.x += sn * sv.x; acc.y += sn * sv.y; acc.z += sn * sv.z; acc.w += sn * sv.w;

    int j   = __ldg(&g_roff[i]);
    int end = __ldg(&g_roff[i + 1]);
    for (; j + 1 < end; j += 2) {
        int   s0 = __ldg(&g_csrc[j]),  s1 = __ldg(&g_csrc[j + 1]);
        float n0 = __ldg(&g_cnorm[j]), n1 = __ldg(&g_cnorm[j + 1]);
        float4 v0 = *(const float4*)(g_lin + (size_t)s0 * HD + c);
        float4 v1 = *(const float4*)(g_lin + (size_t)s1 * HD + c);
        acc.x += n0 * v0.x + n1 * v1.x;
        acc.y += n0 * v0.y + n1 * v1.y;
        acc.z += n0 * v0.z + n1 * v1.z;
        acc.w += n0 * v0.w + n1 * v1.w;
    }
    if (j < end) {
        int   s0 = __ldg(&g_csrc[j]);
        float n0 = __ldg(&g_cnorm[j]);
        float4 v0 = *(const float4*)(g_lin + (size_t)s0 * HD + c);
        acc.x += n0 * v0.x; acc.y += n0 * v0.y;
        acc.z += n0 * v0.z; acc.w += n0 * v0.w;
    }
    acc.x = fmaxf(acc.x, 0.f); acc.y = fmaxf(acc.y, 0.f);
    acc.z = fmaxf(acc.z, 0.f); acc.w = fmaxf(acc.w, 0.f);

    float* out = (outSel == 1) ? g_h1 : g_h2;
    *(float4*)(out + (size_t)i * HD + c) = acc;
}

// ---------------- fused mean-pool + classifier ----------------
__global__ void k_poolout(const float* __restrict__ Wl, const float* __restrict__ bl,
                          float* __restrict__ out) {
    int g = blockIdx.x;
    int t = threadIdx.x;
    int start = g_gstart[g], end = g_gstart[g + 1];
    float s = 0.f;
    for (int r = start; r < end; r++)
        s += g_h1[(size_t)r * HD + t];
    __shared__ float row[HD];
    row[t] = s / fmaxf((float)(end - start), 1.0f);
    __syncthreads();
    if (t < CLS) {
        float o = bl[t];
#pragma unroll 8
        for (int k = 0; k < HD; k++) o += row[k] * Wl[k * CLS + t];
        out[g * CLS + t] = o;
    }
}

// ---------------- launch ----------------
extern "C" void kernel_launch(void* const* d_in, const int* in_sizes, int n_in,
                              void* d_out, int out_size) {
    const float* x     = (const float*)d_in[0];
    const float* W1    = (const float*)d_in[1];
    const float* b1    = (const float*)d_in[2];
    const float* W2    = (const float*)d_in[3];
    const float* b2    = (const float*)d_in[4];
    const float* W3    = (const float*)d_in[5];
    const float* b3    = (const float*)d_in[6];
    const float* Wl    = (const float*)d_in[7];
    const float* bl    = (const float*)d_in[8];
    const void*  ei    = d_in[9];
    const void*  batch = d_in[10];

    int n = in_sizes[0] / HD;
    int E = in_sizes[9] / 2;
    int G = out_size / CLS;
    float* out = (float*)d_out;

    int nb = (n + 255) / 256;
    int eb = (E + 255) / 256;
    int wb = (n + 7) / 8;
    int snb = (n + SCAN_B - 1) / SCAN_B;

    int nTiles = (n + 127) / 128;
    int gemmGrid = nTiles < 296 ? nTiles : 296;   // 2 CTAs/SM persistent

    // launches 1-3
    k_setup<<<nb, 256>>>((const unsigned*)ei, E, n);
    k_hist<<<eb, 256>>>(ei, E);
    k_bounds<<<nb, 256>>>(batch, n, G);
    // launch 4 = ncu capture slot: layer-1 GEMM (independent of CSR build)
    k_gemm<<<gemmGrid, 256>>>(x, 0, W1, n, nTiles);
    // CSR build
    k_scan1<<<snb, SCAN_B>>>(n);
    k_scan2<<<1, SCAN_B>>>(snb);
    k_scan3<<<nb, 256>>>(n, E);
    k_fill<<<eb, 256>>>(ei, E);

    k_gather<<<wb, 256>>>(b1, 1, n);          // -> h1 (relu)
    k_gemm<<<gemmGrid, 256>>>(nullptr, 1, W2, n, nTiles);
    k_gather<<<wb, 256>>>(b2, 2, n);          // -> h2 (relu)
    k_gemm<<<gemmGrid, 256>>>(nullptr, 2, W3, n, nTiles);
    k_gather<<<wb, 256>>>(b3, 1, n);          // -> h1 (relu)
    k_poolout<<<G, HD>>>(Wl, bl, out);
}

// round 14
// speedup vs baseline: 1.3793x; 1.3793x over previous
#include <cuda_runtime.h>
#include <cuda_bf16.h>
#include <cstdint>

#define HD   128
#define NMAX 50000
#define NPAD 50048              // 391 tiles * 128
#define EMAX 600000
#define GMAX 128
#define CLS  10
#define SCAN_B 256

// ---------------- scratch ----------------
__device__ __align__(16) float g_deg [NMAX];
__device__ __align__(16) int   g_cnti[NMAX];
__device__ __align__(16) int   g_roff[NMAX + 1];
__device__ __align__(16) int   g_cur [NMAX];
__device__ __align__(16) int   g_bsum[(NMAX + SCAN_B - 1) / SCAN_B];
__device__ __align__(16) int   g_csrc[EMAX];
__device__ __align__(16) float g_cnorm[EMAX];
__device__ __align__(16) int   g_gstart[GMAX + 1];
__device__ __align__(16) __nv_bfloat16 g_ahi[(size_t)NPAD * HD];  // A hi (bf16)
__device__ __align__(16) __nv_bfloat16 g_alo[(size_t)NPAD * HD];  // A lo (bf16)
__device__ __align__(16) __nv_bfloat16 g_Whi[3 * HD * HD];        // W^T hi, [n][k]
__device__ __align__(16) __nv_bfloat16 g_Wlo[3 * HD * HD];        // W^T lo
__device__ __align__(16) float g_lin[(size_t)NPAD * HD];          // GEMM out fp32
__device__ __align__(16) float g_h1 [(size_t)NMAX * HD];          // layer-3 h (pool)
__device__ int g_is64;

__device__ __forceinline__ int ldidx(const void* p, size_t i) {
    return g_is64 ? (int)((const long long*)p)[i] : ((const int*)p)[i];
}

// ---------------- preprocessing ----------------
__global__ void k_setup(const unsigned* __restrict__ w, int E, int n) {
    int i = blockIdx.x * blockDim.x + threadIdx.x;
    if (i < n) g_cnti[i] = 0;
    if (blockIdx.x == 0) {
        int cnt = E < 256 ? E : 256;
        int t = threadIdx.x;
        int ok = (t < cnt) ? (w[2 * t + 1] == 0u) : 1;
        ok = __syncthreads_and(ok);
        if (t == 0) g_is64 = ok;
    }
}
// fused bf16 hi/lo conversion: x rows + all 3 weight matrices (transposed [n][k])
__global__ void k_cvt(const float* __restrict__ x,
                      const float* __restrict__ W1, const float* __restrict__ W2,
                      const float* __restrict__ W3, int n) {
    long long idx = (long long)blockIdx.x * 256 + threadIdx.x;
    long long nx = (long long)n * HD;
    if (idx < nx) {
        float v = x[idx];
        __nv_bfloat16 h = __float2bfloat16(v);
        g_ahi[idx] = h;
        g_alo[idx] = __float2bfloat16(v - __bfloat162float(h));
    } else {
        long long j = idx - nx;
        if (j < 3 * HD * HD) {
            int layer = (int)(j / (HD * HD));
            int r = (int)(j % (HD * HD));
            int nn = r >> 7, k = r & 127;             // output [nn][k] = W[k][nn]
            const float* W = layer == 0 ? W1 : (layer == 1 ? W2 : W3);
            float v = W[k * HD + nn];
            __nv_bfloat16 h = __float2bfloat16(v);
            g_Whi[j] = h;
            g_Wlo[j] = __float2bfloat16(v - __bfloat162float(h));
        }
    }
}
__global__ void k_bounds(const void* __restrict__ batch, int n, int G) {
    int i = blockIdx.x * blockDim.x + threadIdx.x;
    if (i >= n) return;
    int g = ldidx(batch, i);
    if (i == 0) {
        for (int q = 0; q <= g; q++) g_gstart[q] = 0;
    } else {
        int gp = ldidx(batch, i - 1);
        for (int q = gp + 1; q <= g; q++) g_gstart[q] = i;
    }
    if (i == n - 1) {
        for (int q = g + 1; q <= G; q++) g_gstart[q] = n;
    }
}
__global__ void k_hist(const void* __restrict__ ei, int E) {
    int e = blockIdx.x * blockDim.x + threadIdx.x;
    if (e < E) atomicAdd(&g_cnti[ldidx(ei, (size_t)E + e)], 1);
}
__global__ void k_scan1(int n) {
    __shared__ int s[SCAN_B];
    int i = blockIdx.x * SCAN_B + threadIdx.x;
    int v = (i < n) ? g_cnti[i] : 0;
    if (i < n) g_deg[i] = rsqrtf(1.0f + (float)v);
    s[threadIdx.x] = v;
    __syncthreads();
    int acc = v;
#pragma unroll
    for (int off = 1; off < SCAN_B; off <<= 1) {
        int add = (threadIdx.x >= off) ? s[threadIdx.x - off] : 0;
        __syncthreads();
        acc += add;
        s[threadIdx.x] = acc;
        __syncthreads();
    }
    if (i < n) g_roff[i] = acc - v;
    if (threadIdx.x == SCAN_B - 1) g_bsum[blockIdx.x] = acc;
}
// fused: per-block prefix over bsum + finalize roff/cur (replaces scan2+scan3)
__global__ void k_scan2b(int n, int E, int nb) {
    __shared__ int sred[SCAN_B];
    int bid = blockIdx.x, t = threadIdx.x;
    int v = (t < nb && t < bid) ? g_bsum[t] : 0;
    sred[t] = v;
    __syncthreads();
#pragma unroll
    for (int off = SCAN_B / 2; off > 0; off >>= 1) {
        if (t < off) sred[t] += sred[t + off];
        __syncthreads();
    }
    int prefix = sred[0];
    int i = bid * SCAN_B + t;
    if (i < n) {
        int r = g_roff[i] + prefix;
        g_roff[i] = r;
        g_cur[i] = r;
    }
    if (bid == nb - 1 && t == 0) g_roff[n] = E;
}
__global__ void k_fill(const void* __restrict__ ei, int E) {
    int e = blockIdx.x * blockDim.x + threadIdx.x;
    if (e >= E) return;
    int s = ldidx(ei, e);
    int d = ldidx(ei, (size_t)E + e);
    int pos = atomicAdd(&g_cur[d], 1);
    g_csrc[pos] = s;
    g_cnorm[pos] = g_deg[s] * g_deg[d];
}

// ---------------- HMMA GEMM: g_lin = A @ W  (mma.sync bf16, hi/lo x3) -----
// One CTA per 128x128 tile, K=128 resident in smem. 8 warps (4x2): warp tile
// 32x64, frags m16n8k16. A row-major [m][k] and W^T [n][k] both feed plain
// (non-trans) ldmatrix. Rows padded to 272B (17x16B) -> ldmatrix
// conflict-free. 3 passes: AhBh + AhBl + AlBh accumulate in fp32.
#define KPADB 272                              // bytes per padded row
#define MAT_B (128 * KPADB)                    // one 128x128 bf16 matrix

__device__ __forceinline__ uint32_t smem_u32(const void* p) {
    uint32_t a;
    asm("{ .reg .u64 t; cvta.to.shared.u64 t, %1; cvt.u32.u64 %0, t; }"
        : "=r"(a) : "l"(p));
    return a;
}
#define LDSM4(r0, r1, r2, r3, a) \
    asm volatile("ldmatrix.sync.aligned.m8n8.x4.shared.b16 {%0,%1,%2,%3}, [%4];" \
                 : "=r"(r0), "=r"(r1), "=r"(r2), "=r"(r3) : "r"(a))
#define MMA16816(c, a, b) \
    asm volatile("mma.sync.aligned.m16n8k16.row.col.f32.bf16.bf16.f32 " \
                 "{%0,%1,%2,%3}, {%4,%5,%6,%7}, {%8,%9}, {%0,%1,%2,%3};" \
                 : "+f"((c)[0]), "+f"((c)[1]), "+f"((c)[2]), "+f"((c)[3]) \
                 : "r"((a)[0]), "r"((a)[1]), "r"((a)[2]), "r"((a)[3]), \
                   "r"((b)[0]), "r"((b)[1]))

__global__ __launch_bounds__(256) void k_mma(int layer, int M) {
    extern __shared__ __align__(16) char sm[];
    const int SM_AH = 0, SM_AL = MAT_B, SM_BH = 2 * MAT_B, SM_BL = 3 * MAT_B;
    const uint32_t smb = smem_u32(sm);
    const int tid = threadIdx.x, wid = tid >> 5, lane = tid & 31;
    const int rowBase = blockIdx.x * 128;

    const __nv_bfloat16* Ah = g_ahi + (size_t)rowBase * HD;
    const __nv_bfloat16* Al = g_alo + (size_t)rowBase * HD;
    const __nv_bfloat16* Bh = g_Whi + layer * HD * HD;
    const __nv_bfloat16* Bl = g_Wlo + layer * HD * HD;

    // load 4 matrices into padded smem: 128 rows x 16 chunks of 16B each
#pragma unroll
    for (int q = 0; q < 8; q++) {
        int idx = q * 256 + tid;
        int row = idx >> 4, ch = idx & 15;
        int so = row * KPADB + ch * 16;
        int go = row * HD + ch * 8;
        *(uint4*)(sm + SM_AH + so) = *(const uint4*)(Ah + go);
        *(uint4*)(sm + SM_AL + so) = *(const uint4*)(Al + go);
        *(uint4*)(sm + SM_BH + so) = *(const uint4*)(Bh + go);
        *(uint4*)(sm + SM_BL + so) = *(const uint4*)(Bl + go);
    }
    __syncthreads();

    const int mb = (wid & 3) * 32;            // warp rows mb..mb+31
    const int nb = (wid >> 2) * 64;           // warp cols nb..nb+63

    // ldmatrix lane addresses (within warp):
    // A frag i: row = mb + i*16 + (lane&15), colbyte = ks*32 + (lane>>4)*16
    const int aRow = (lane & 15);
    const int aCol = (lane >> 4) * 16;
    // B frag pair (j, j+1): row = nb + (lane>>4)*8 + (lane&7),
    //                       colbyte = ks*32 + ((lane>>3)&1)*16
    const int bRow = ((lane >> 4) * 8) + (lane & 7);
    const int bCol = ((lane >> 3) & 1) * 16;

    float acc[2][8][4];
#pragma unroll
    for (int i = 0; i < 2; i++)
#pragma unroll
        for (int j = 0; j < 8; j++)
#pragma unroll
            for (int c = 0; c < 4; c++) acc[i][j][c] = 0.f;

#pragma unroll
    for (int ks = 0; ks < 8; ks++) {
        uint32_t ah[2][4], al[2][4], bh[8][2], bl[8][2];
#pragma unroll
        for (int i = 0; i < 2; i++) {
            uint32_t a = smb + (uint32_t)((mb + i * 16 + aRow) * KPADB + ks * 32 + aCol);
            LDSM4(ah[i][0], ah[i][1], ah[i][2], ah[i][3], a + SM_AH);
            LDSM4(al[i][0], al[i][1], al[i][2], al[i][3], a + SM_AL);
        }
#pragma unroll
        for (int jp = 0; jp < 4; jp++) {
            uint32_t a = smb + (uint32_t)((nb + jp * 16 + bRow) * KPADB + ks * 32 + bCol);
            LDSM4(bh[2 * jp][0], bh[2 * jp][1], bh[2 * jp + 1][0], bh[2 * jp + 1][1],
                  a + SM_BH);
            LDSM4(bl[2 * jp][0], bl[2 * jp][1], bl[2 * jp + 1][0], bl[2 * jp + 1][1],
                  a + SM_BL);
        }
#pragma unroll
        for (int i = 0; i < 2; i++)
#pragma unroll
            for (int j = 0; j < 8; j++) {
                MMA16816(acc[i][j], ah[i], bh[j]);
                MMA16816(acc[i][j], ah[i], bl[j]);
                MMA16816(acc[i][j], al[i], bh[j]);
            }
    }

    // epilogue: c0/c1 -> (row, col..col+1), c2/c3 -> (row+8, ...)
    const int cRow = lane >> 2;
    const int cCol = (lane & 3) * 2;
#pragma unroll
    for (int i = 0; i < 2; i++) {
        int r0 = rowBase + mb + i * 16 + cRow;
#pragma unroll
        for (int j = 0; j < 8; j++) {
            int col = nb + j * 8 + cCol;
            if (r0 < M)
                *(float2*)(g_lin + (size_t)r0 * HD + col) =
                    make_float2(acc[i][j][0], acc[i][j][1]);
            if (r0 + 8 < M)
                *(float2*)(g_lin + (size_t)(r0 + 8) * HD + col) =
                    make_float2(acc[i][j][2], acc[i][j][3]);
        }
    }
}

// ---------------- CSR gather ----------------
// mode 1: write bf16 hi/lo (feeds next GEMM); mode 0: write fp32 h1 (pool)
__global__ __launch_bounds__(256) void k_gather(
    const float* __restrict__ bias, int mode, int n)
{
    int i = blockIdx.x * 8 + (threadIdx.x >> 5);
    if (i >= n) return;
    int c = (threadIdx.x & 31) * 4;

    float di = g_deg[i];
    float sn = di * di;
    float4 acc = __ldg((const float4*)(bias + c));
    float4 sv = *(const float4*)(g_lin + (size_t)i * HD + c);
    acc.x += sn * sv.x; acc.y += sn * sv.y; acc.z += sn * sv.z; acc.w += sn * sv.w;

    int j   = __ldg(&g_roff[i]);
    int end = __ldg(&g_roff[i + 1]);
    for (; j + 1 < end; j += 2) {
        int   s0 = __ldg(&g_csrc[j]),  s1 = __ldg(&g_csrc[j + 1]);
        float n0 = __ldg(&g_cnorm[j]), n1 = __ldg(&g_cnorm[j + 1]);
        float4 v0 = *(const float4*)(g_lin + (size_t)s0 * HD + c);
        float4 v1 = *(const float4*)(g_lin + (size_t)s1 * HD + c);
        acc.x += n0 * v0.x + n1 * v1.x;
        acc.y += n0 * v0.y + n1 * v1.y;
        acc.z += n0 * v0.z + n1 * v1.z;
        acc.w += n0 * v0.w + n1 * v1.w;
    }
    if (j < end) {
        int   s0 = __ldg(&g_csrc[j]);
        float n0 = __ldg(&g_cnorm[j]);
        float4 v0 = *(const float4*)(g_lin + (size_t)s0 * HD + c);
        acc.x += n0 * v0.x; acc.y += n0 * v0.y;
        acc.z += n0 * v0.z; acc.w += n0 * v0.w;
    }
    acc.x = fmaxf(acc.x, 0.f); acc.y = fmaxf(acc.y, 0.f);
    acc.z = fmaxf(acc.z, 0.f); acc.w = fmaxf(acc.w, 0.f);

    if (mode == 0) {
        *(float4*)(g_h1 + (size_t)i * HD + c) = acc;
    } else {
        __nv_bfloat16 hx = __float2bfloat16(acc.x), hy = __float2bfloat16(acc.y);
        __nv_bfloat16 hz = __float2bfloat16(acc.z), hw = __float2bfloat16(acc.w);
        __nv_bfloat162 p0, p1;
        p0.x = hx; p0.y = hy; p1.x = hz; p1.y = hw;
        *(__nv_bfloat162*)(g_ahi + (size_t)i * HD + c)     = p0;
        *(__nv_bfloat162*)(g_ahi + (size_t)i * HD + c + 2) = p1;
        __nv_bfloat162 q0, q1;
        q0.x = __float2bfloat16(acc.x - __bfloat162float(hx));
        q0.y = __float2bfloat16(acc.y - __bfloat162float(hy));
        q1.x = __float2bfloat16(acc.z - __bfloat162float(hz));
        q1.y = __float2bfloat16(acc.w - __bfloat162float(hw));
        *(__nv_bfloat162*)(g_alo + (size_t)i * HD + c)     = q0;
        *(__nv_bfloat162*)(g_alo + (size_t)i * HD + c + 2) = q1;
    }
}

// ---------------- fused mean-pool + classifier ----------------
__global__ void k_poolout(const float* __restrict__ Wl, const float* __restrict__ bl,
                          float* __restrict__ out) {
    int g = blockIdx.x;
    int t = threadIdx.x;
    int start = g_gstart[g], end = g_gstart[g + 1];
    float s = 0.f;
    for (int r = start; r < end; r++)
        s += g_h1[(size_t)r * HD + t];
    __shared__ float row[HD];
    row[t] = s / fmaxf((float)(end - start), 1.0f);
    __syncthreads();
    if (t < CLS) {
        float o = bl[t];
#pragma unroll 8
        for (int k = 0; k < HD; k++) o += row[k] * Wl[k * CLS + t];
        out[g * CLS + t] = o;
    }
}

// ---------------- launch ----------------
extern "C" void kernel_launch(void* const* d_in, const int* in_sizes, int n_in,
                              void* d_out, int out_size) {
    const float* x     = (const float*)d_in[0];
    const float* W1    = (const float*)d_in[1];
    const float* b1    = (const float*)d_in[2];
    const float* W2    = (const float*)d_in[3];
    const float* b2    = (const float*)d_in[4];
    const float* W3    = (const float*)d_in[5];
    const float* b3    = (const float*)d_in[6];
    const float* Wl    = (const float*)d_in[7];
    const float* bl    = (const float*)d_in[8];
    const void*  ei    = d_in[9];
    const void*  batch = d_in[10];

    int n = in_sizes[0] / HD;
    int E = in_sizes[9] / 2;
    int G = out_size / CLS;
    float* out = (float*)d_out;

    int nb = (n + 255) / 256;
    int eb = (E + 255) / 256;
    int wb = (n + 7) / 8;
    int snb = (n + SCAN_B - 1) / SCAN_B;
    int nTiles = (n + 127) / 128;

    long long cvtElems = (long long)n * HD + 3 * HD * HD;
    int cvb = (int)((cvtElems + 255) / 256);

    const int MMA_SMEM = 4 * MAT_B;           // 136 KB dynamic
    static int attrSet = 0;
    if (!attrSet) {
        cudaFuncSetAttribute(k_mma, cudaFuncAttributeMaxDynamicSharedMemorySize,
                             MMA_SMEM);
        attrSet = 1;
    }

    // launches 1-3
    k_setup<<<nb, 256>>>((const unsigned*)ei, E, n);
    k_cvt<<<cvb, 256>>>(x, W1, W2, W3, n);
    k_hist<<<eb, 256>>>(ei, E);
    // launch 4 = ncu capture slot: layer-1 tensor GEMM
    k_mma<<<nTiles, 256, MMA_SMEM>>>(0, n);
    // CSR build
    k_bounds<<<nb, 256>>>(batch, n, G);
    k_scan1<<<snb, SCAN_B>>>(n);
    k_scan2b<<<snb, SCAN_B>>>(n, E, snb);
    k_fill<<<eb, 256>>>(ei, E);

    k_gather<<<wb, 256>>>(b1, 1, n);              // -> bf16 hi/lo
    k_mma<<<nTiles, 256, MMA_SMEM>>>(1, n);
    k_gather<<<wb, 256>>>(b2, 1, n);              // -> bf16 hi/lo
    k_mma<<<nTiles, 256, MMA_SMEM>>>(2, n);
    k_gather<<<wb, 256>>>(b3, 0, n);              // -> fp32 h1
    k_poolout<<<G, HD>>>(Wl, bl, out);
}